// round 1
// baseline (speedup 1.0000x reference)
#include <cuda_runtime.h>
#include <cuda_bf16.h>

// Problem dims
#define BB 8
#define SS 1024          // IMG*IMG
#define EE 768           // D_EMBED == D_MODEL
#define NH 12
#define DD 64

// ---------------- scratch (device globals; no allocs allowed) ----------------
__device__ float g_q[BB * SS * EE];
__device__ float g_k[BB * SS * EE];
__device__ float g_v[BB * SS * EE];
__device__ float g_ctx[BB * SS * EE];

// ---------------- GEMM tile params ----------------
#define BM 128
#define BN 64
#define BK 16

// =============================================================================
// Kernel 1: QKV projection.
// Per batch b, matrix mat in {q,k,v}:
//   Y[s, o] = sum_c X[b][c][s] * W[o][c] + bias[o]
// X is [768(c), 1024(s)] (K-major => direct [k][m] smem load, coalesced).
// W is [768(o), 768(c)]  (row k-contiguous => transpose-store into Bs[k][n]).
// Output written as [B, S, 768].
// =============================================================================
__global__ __launch_bounds__(256) void proj_kernel(
    const float* __restrict__ xq, const float* __restrict__ xk, const float* __restrict__ xv,
    const float* __restrict__ wq, const float* __restrict__ wk, const float* __restrict__ wv,
    const float* __restrict__ bq, const float* __restrict__ bk, const float* __restrict__ bv)
{
    const int mat = blockIdx.z >> 3;
    const int b   = blockIdx.z & 7;

    const float* x;
    const float* w;
    const float* bi;
    float* y;
    if (mat == 0)      { x = xq; w = wq; bi = bq; y = g_q; }
    else if (mat == 1) { x = xk; w = wk; bi = bk; y = g_k; }
    else               { x = xv; w = wv; bi = bv; y = g_v; }

    x += (size_t)b * EE * SS;   // [c][s]
    y += (size_t)b * SS * EE;   // [s][o]

    const int m0 = blockIdx.x * BM;   // s tile
    const int n0 = blockIdx.y * BN;   // o tile

    __shared__ float As[BK][BM];
    __shared__ float Bs[BK][BN];

    const int tid = threadIdx.x;
    const int tn = tid & 15;
    const int tm = tid >> 4;

    float acc[8][4];
    #pragma unroll
    for (int i = 0; i < 8; i++)
        #pragma unroll
        for (int j = 0; j < 4; j++) acc[i][j] = 0.f;

    for (int k0 = 0; k0 < EE; k0 += BK) {
        // Load A tile: [16 k][128 m], coalesced float4 along m
        #pragma unroll
        for (int p = 0; p < 2; p++) {
            int idx = tid + p * 256;           // 0..511 float4 slots
            int row = idx >> 5;                // k within tile
            int col = (idx & 31) << 2;         // m within tile
            float4 v4 = *(const float4*)(x + (size_t)(k0 + row) * SS + m0 + col);
            *(float4*)(&As[row][col]) = v4;
        }
        // Load W tile: 64 rows(n) x 16(k), transpose-store
        {
            int r  = tid >> 2;
            int kq = (tid & 3) << 2;
            float4 v4 = *(const float4*)(w + (size_t)(n0 + r) * EE + k0 + kq);
            Bs[kq + 0][r] = v4.x; Bs[kq + 1][r] = v4.y;
            Bs[kq + 2][r] = v4.z; Bs[kq + 3][r] = v4.w;
        }
        __syncthreads();

        #pragma unroll
        for (int kk = 0; kk < BK; kk++) {
            float a[8], bb[4];
            *(float4*)&a[0] = *(float4*)&As[kk][tm * 8];
            *(float4*)&a[4] = *(float4*)&As[kk][tm * 8 + 4];
            *(float4*)&bb[0] = *(float4*)&Bs[kk][tn * 4];
            #pragma unroll
            for (int i = 0; i < 8; i++)
                #pragma unroll
                for (int j = 0; j < 4; j++)
                    acc[i][j] += a[i] * bb[j];
        }
        __syncthreads();
    }

    float bvv[4];
    *(float4*)bvv = *(const float4*)(bi + n0 + tn * 4);
    #pragma unroll
    for (int i = 0; i < 8; i++) {
        float4 o4;
        o4.x = acc[i][0] + bvv[0];
        o4.y = acc[i][1] + bvv[1];
        o4.z = acc[i][2] + bvv[2];
        o4.w = acc[i][3] + bvv[3];
        *(float4*)(y + (size_t)(m0 + tm * 8 + i) * EE + n0 + tn * 4) = o4;
    }
}

// =============================================================================
// Kernel 2: attention for one (b, h, 32-row q tile).
// scores -> softmax (keep unnormalized exp in smem, write normalized probs
// coalesced) -> ctx = P @ V (normalize in epilogue).
// Dynamic smem: Qs[64][32] + Ks[64][64] + Vs[64][64] + Sc[32][1024]
// =============================================================================
#define ATTN_SMEM_FLOATS (2048 + 4096 + 4096 + 32768)
#define ATTN_SMEM_BYTES  (ATTN_SMEM_FLOATS * 4)

__global__ __launch_bounds__(256) void attn_kernel(float* __restrict__ probs)
{
    extern __shared__ float sm[];
    float* Qs = sm;                  // [d][q]   64*32
    float* Ks = sm + 2048;           // [d][k]   64*64
    float* Vs = sm + 2048 + 4096;    // [k][d]   64*64
    float* Sc = sm + 2048 + 8192;    // [q][k]   32*1024

    __shared__ float red[32][8];
    __shared__ float invs[32];

    const int tid = threadIdx.x;
    const int qt  = blockIdx.x;      // 0..31
    const int bh  = blockIdx.y;      // 0..95
    const int b   = bh / NH;
    const int h   = bh % NH;

    const float* qptr = g_q + ((size_t)b * SS + qt * 32) * EE + h * DD;
    const float* kbase = g_k + (size_t)b * SS * EE + h * DD;
    const float* vbase = g_v + (size_t)b * SS * EE + h * DD;

    // ---- load Q tile (transposed: Qs[d][q]) ----
    #pragma unroll
    for (int p = 0; p < 2; p++) {
        int idx = tid + p * 256;        // 0..511 float4
        int r   = idx >> 4;             // q row 0..31
        int dq  = (idx & 15) << 2;      // d
        float4 v4 = *(const float4*)(qptr + (size_t)r * EE + dq);
        Qs[(dq + 0) * 32 + r] = v4.x;
        Qs[(dq + 1) * 32 + r] = v4.y;
        Qs[(dq + 2) * 32 + r] = v4.z;
        Qs[(dq + 3) * 32 + r] = v4.w;
    }
    __syncthreads();

    const int tq = tid >> 4;   // 0..15 (2 q rows each)
    const int tk = tid & 15;   // 0..15 (4 k cols / 4 d cols each)

    // ---- scores ----
    for (int kt = 0; kt < 16; kt++) {
        const float* kptr = kbase + (size_t)(kt * 64) * EE;
        #pragma unroll
        for (int p = 0; p < 4; p++) {
            int idx = tid + p * 256;    // 0..1023 float4
            int r   = idx >> 4;         // k row 0..63
            int dq  = (idx & 15) << 2;
            float4 v4 = *(const float4*)(kptr + (size_t)r * EE + dq);
            Ks[(dq + 0) * 64 + r] = v4.x;
            Ks[(dq + 1) * 64 + r] = v4.y;
            Ks[(dq + 2) * 64 + r] = v4.z;
            Ks[(dq + 3) * 64 + r] = v4.w;
        }
        __syncthreads();

        float acc[2][4];
        #pragma unroll
        for (int i = 0; i < 2; i++)
            #pragma unroll
            for (int j = 0; j < 4; j++) acc[i][j] = 0.f;

        #pragma unroll 8
        for (int d = 0; d < 64; d++) {
            float2 a2 = *(float2*)&Qs[d * 32 + tq * 2];
            float4 b4 = *(float4*)&Ks[d * 64 + tk * 4];
            acc[0][0] += a2.x * b4.x; acc[0][1] += a2.x * b4.y;
            acc[0][2] += a2.x * b4.z; acc[0][3] += a2.x * b4.w;
            acc[1][0] += a2.y * b4.x; acc[1][1] += a2.y * b4.y;
            acc[1][2] += a2.y * b4.z; acc[1][3] += a2.y * b4.w;
        }
        #pragma unroll
        for (int i = 0; i < 2; i++)
            #pragma unroll
            for (int j = 0; j < 4; j++)
                Sc[(tq * 2 + i) * 1024 + kt * 64 + tk * 4 + j] = acc[i][j] * 0.125f;
        __syncthreads();
    }

    // ---- softmax over each of 32 rows (8 threads / row) ----
    {
        const int row = tid >> 3;
        const int j   = tid & 7;
        float mx = -3.4e38f;
        for (int c = j; c < 1024; c += 8) mx = fmaxf(mx, Sc[row * 1024 + c]);
        red[row][j] = mx;
        __syncthreads();
        #pragma unroll
        for (int t = 0; t < 8; t++) mx = fmaxf(mx, red[row][t]);
        __syncthreads();   // all reads of red done before sum overwrites

        float sum = 0.f;
        for (int c = j; c < 1024; c += 8) {
            float e = __expf(Sc[row * 1024 + c] - mx);
            Sc[row * 1024 + c] = e;   // keep unnormalized
            sum += e;
        }
        red[row][j] = sum;
        __syncthreads();
        float s = 0.f;
        #pragma unroll
        for (int t = 0; t < 8; t++) s += red[row][t];
        if (j == 0) invs[row] = 1.f / s;
    }
    __syncthreads();

    // ---- coalesced normalized probs write ----
    {
        float* pbase = probs + (((size_t)bh * SS) + qt * 32) * SS;
        for (int idx = tid; idx < 32 * 1024; idx += 256) {
            int row = idx >> 10;
            pbase[idx] = Sc[idx] * invs[row];
        }
    }

    // ---- ctx = P @ V ----
    float cac[2][4];
    #pragma unroll
    for (int i = 0; i < 2; i++)
        #pragma unroll
        for (int j = 0; j < 4; j++) cac[i][j] = 0.f;

    for (int kt = 0; kt < 16; kt++) {
        const float* vptr = vbase + (size_t)(kt * 64) * EE;
        __syncthreads();   // previous Vs consumers done
        #pragma unroll
        for (int p = 0; p < 4; p++) {
            int idx = tid + p * 256;
            int r   = idx >> 4;
            int dq  = (idx & 15) << 2;
            *(float4*)&Vs[r * 64 + dq] = *(const float4*)(vptr + (size_t)r * EE + dq);
        }
        __syncthreads();

        #pragma unroll 8
        for (int kk = 0; kk < 64; kk++) {
            float p0 = Sc[(tq * 2 + 0) * 1024 + kt * 64 + kk];
            float p1 = Sc[(tq * 2 + 1) * 1024 + kt * 64 + kk];
            float4 v4 = *(float4*)&Vs[kk * 64 + tk * 4];
            cac[0][0] += p0 * v4.x; cac[0][1] += p0 * v4.y;
            cac[0][2] += p0 * v4.z; cac[0][3] += p0 * v4.w;
            cac[1][0] += p1 * v4.x; cac[1][1] += p1 * v4.y;
            cac[1][2] += p1 * v4.z; cac[1][3] += p1 * v4.w;
        }
    }

    #pragma unroll
    for (int i = 0; i < 2; i++) {
        float ci = invs[tq * 2 + i];
        int s = qt * 32 + tq * 2 + i;
        float4 o4;
        o4.x = cac[i][0] * ci; o4.y = cac[i][1] * ci;
        o4.z = cac[i][2] * ci; o4.w = cac[i][3] * ci;
        *(float4*)(g_ctx + ((size_t)b * SS + s) * EE + h * DD + tk * 4) = o4;
    }
}

// =============================================================================
// Kernel 3: output projection.
//   out[b][o][s] = sum_c ctx[b][s][c] * fc_w[o][c] + fc_b[o]
// M = o (768), N = s (1024), K = c (768). Both operands k-contiguous
// => transpose-store smem loads. Output s-contiguous => coalesced epilogue.
// =============================================================================
__global__ __launch_bounds__(256) void fc_kernel(
    const float* __restrict__ fcw, const float* __restrict__ fcb,
    float* __restrict__ out)
{
    const int b  = blockIdx.z;
    const int m0 = blockIdx.x * BM;   // o tile (768/128 = 6)
    const int n0 = blockIdx.y * BN;   // s tile (1024/64 = 16)

    const float* ctx = g_ctx + (size_t)b * SS * EE;

    __shared__ float As[BK][BM];
    __shared__ float Bs[BK][BN];

    const int tid = threadIdx.x;
    const int tn = tid & 15;
    const int tm = tid >> 4;

    float acc[8][4];
    #pragma unroll
    for (int i = 0; i < 8; i++)
        #pragma unroll
        for (int j = 0; j < 4; j++) acc[i][j] = 0.f;

    for (int k0 = 0; k0 < EE; k0 += BK) {
        // A = fc_w [128 m rows][16 k], transpose-store
        #pragma unroll
        for (int p = 0; p < 2; p++) {
            int idx = tid + p * 256;       // 0..511 float4
            int row = idx >> 2;            // m 0..127
            int kq  = (idx & 3) << 2;
            float4 v4 = *(const float4*)(fcw + (size_t)(m0 + row) * EE + k0 + kq);
            As[kq + 0][row] = v4.x; As[kq + 1][row] = v4.y;
            As[kq + 2][row] = v4.z; As[kq + 3][row] = v4.w;
        }
        // B = ctx [64 n rows][16 k], transpose-store
        {
            int r  = tid >> 2;
            int kq = (tid & 3) << 2;
            float4 v4 = *(const float4*)(ctx + (size_t)(n0 + r) * EE + k0 + kq);
            Bs[kq + 0][r] = v4.x; Bs[kq + 1][r] = v4.y;
            Bs[kq + 2][r] = v4.z; Bs[kq + 3][r] = v4.w;
        }
        __syncthreads();

        #pragma unroll
        for (int kk = 0; kk < BK; kk++) {
            float a[8], bb[4];
            *(float4*)&a[0] = *(float4*)&As[kk][tm * 8];
            *(float4*)&a[4] = *(float4*)&As[kk][tm * 8 + 4];
            *(float4*)&bb[0] = *(float4*)&Bs[kk][tn * 4];
            #pragma unroll
            for (int i = 0; i < 8; i++)
                #pragma unroll
                for (int j = 0; j < 4; j++)
                    acc[i][j] += a[i] * bb[j];
        }
        __syncthreads();
    }

    #pragma unroll
    for (int i = 0; i < 8; i++) {
        int o = m0 + tm * 8 + i;
        float fb = fcb[o];
        float4 o4;
        o4.x = acc[i][0] + fb; o4.y = acc[i][1] + fb;
        o4.z = acc[i][2] + fb; o4.w = acc[i][3] + fb;
        *(float4*)(out + ((size_t)b * EE + o) * SS + n0 + tn * 4) = o4;
    }
}

// =============================================================================
extern "C" void kernel_launch(void* const* d_in, const int* in_sizes, int n_in,
                              void* d_out, int out_size)
{
    const float* q_img = (const float*)d_in[0];
    const float* k_img = (const float*)d_in[1];
    const float* v_img = (const float*)d_in[2];
    const float* wq_w  = (const float*)d_in[3];
    const float* wq_b  = (const float*)d_in[4];
    const float* wk_w  = (const float*)d_in[5];
    const float* wk_b  = (const float*)d_in[6];
    const float* wv_w  = (const float*)d_in[7];
    const float* wv_b  = (const float*)d_in[8];
    const float* fc_w  = (const float*)d_in[9];
    const float* fc_b  = (const float*)d_in[10];

    float* out   = (float*)d_out;
    float* probs = out + (size_t)BB * EE * SS;   // tuple output: (out, probs)

    // 1) QKV projections
    dim3 g1(SS / BM, EE / BN, 3 * BB);
    proj_kernel<<<g1, 256>>>(q_img, k_img, v_img,
                             wq_w, wk_w, wv_w,
                             wq_b, wk_b, wv_b);

    // 2) attention (+ probs output)
    cudaFuncSetAttribute(attn_kernel, cudaFuncAttributeMaxDynamicSharedMemorySize,
                         ATTN_SMEM_BYTES);
    attn_kernel<<<dim3(SS / 32, BB * NH), 256, ATTN_SMEM_BYTES>>>(probs);

    // 3) output projection
    fc_kernel<<<dim3(EE / BM, SS / BN, BB), 256>>>(fc_w, fc_b, out);
}

// round 2
// speedup vs baseline: 1.5417x; 1.5417x over previous
#include <cuda_runtime.h>
#include <cuda_bf16.h>
#include <cstdint>

// Problem dims
#define BB 8
#define SS 1024          // IMG*IMG
#define EE 768           // D_EMBED == D_MODEL
#define NH 12
#define DD 64

// ---------------- scratch (device globals; no allocs allowed) ----------------
__device__ float g_q[BB * SS * EE];
__device__ float g_k[BB * SS * EE];
__device__ float g_v[BB * SS * EE];
__device__ float g_ctx[BB * SS * EE];

// ---------------- GEMM tile params (proj / fc) ----------------
#define BM 128
#define BN 64
#define BK 16

// =============================================================================
// tf32 mma helpers
// =============================================================================
__device__ __forceinline__ void split_tf32(float x, uint32_t& hi, uint32_t& lo) {
    asm("cvt.rna.tf32.f32 %0, %1;" : "=r"(hi) : "f"(x));
    float r = x - __uint_as_float(hi);
    asm("cvt.rna.tf32.f32 %0, %1;" : "=r"(lo) : "f"(r));
}

__device__ __forceinline__ void mma_tf32(float* d, const uint32_t* a, const uint32_t* b) {
    asm volatile(
        "mma.sync.aligned.m16n8k8.row.col.f32.tf32.tf32.f32 "
        "{%0,%1,%2,%3}, {%4,%5,%6,%7}, {%8,%9}, {%0,%1,%2,%3};"
        : "+f"(d[0]), "+f"(d[1]), "+f"(d[2]), "+f"(d[3])
        : "r"(a[0]), "r"(a[1]), "r"(a[2]), "r"(a[3]),
          "r"(b[0]), "r"(b[1]));
}

// =============================================================================
// Kernel 1: QKV projection (unchanged from round 1; ~46 TF/s fp32)
// =============================================================================
__global__ __launch_bounds__(256) void proj_kernel(
    const float* __restrict__ xq, const float* __restrict__ xk, const float* __restrict__ xv,
    const float* __restrict__ wq, const float* __restrict__ wk, const float* __restrict__ wv,
    const float* __restrict__ bq, const float* __restrict__ bk, const float* __restrict__ bv)
{
    const int mat = blockIdx.z >> 3;
    const int b   = blockIdx.z & 7;

    const float* x;
    const float* w;
    const float* bi;
    float* y;
    if (mat == 0)      { x = xq; w = wq; bi = bq; y = g_q; }
    else if (mat == 1) { x = xk; w = wk; bi = bk; y = g_k; }
    else               { x = xv; w = wv; bi = bv; y = g_v; }

    x += (size_t)b * EE * SS;   // [c][s]
    y += (size_t)b * SS * EE;   // [s][o]

    const int m0 = blockIdx.x * BM;   // s tile
    const int n0 = blockIdx.y * BN;   // o tile

    __shared__ float As[BK][BM];
    __shared__ float Bs[BK][BN];

    const int tid = threadIdx.x;
    const int tn = tid & 15;
    const int tm = tid >> 4;

    float acc[8][4];
    #pragma unroll
    for (int i = 0; i < 8; i++)
        #pragma unroll
        for (int j = 0; j < 4; j++) acc[i][j] = 0.f;

    for (int k0 = 0; k0 < EE; k0 += BK) {
        #pragma unroll
        for (int p = 0; p < 2; p++) {
            int idx = tid + p * 256;
            int row = idx >> 5;
            int col = (idx & 31) << 2;
            float4 v4 = *(const float4*)(x + (size_t)(k0 + row) * SS + m0 + col);
            *(float4*)(&As[row][col]) = v4;
        }
        {
            int r  = tid >> 2;
            int kq = (tid & 3) << 2;
            float4 v4 = *(const float4*)(w + (size_t)(n0 + r) * EE + k0 + kq);
            Bs[kq + 0][r] = v4.x; Bs[kq + 1][r] = v4.y;
            Bs[kq + 2][r] = v4.z; Bs[kq + 3][r] = v4.w;
        }
        __syncthreads();

        #pragma unroll
        for (int kk = 0; kk < BK; kk++) {
            float a[8], bb[4];
            *(float4*)&a[0] = *(float4*)&As[kk][tm * 8];
            *(float4*)&a[4] = *(float4*)&As[kk][tm * 8 + 4];
            *(float4*)&bb[0] = *(float4*)&Bs[kk][tn * 4];
            #pragma unroll
            for (int i = 0; i < 8; i++)
                #pragma unroll
                for (int j = 0; j < 4; j++)
                    acc[i][j] += a[i] * bb[j];
        }
        __syncthreads();
    }

    float bvv[4];
    *(float4*)bvv = *(const float4*)(bi + n0 + tn * 4);
    #pragma unroll
    for (int i = 0; i < 8; i++) {
        float4 o4;
        o4.x = acc[i][0] + bvv[0];
        o4.y = acc[i][1] + bvv[1];
        o4.z = acc[i][2] + bvv[2];
        o4.w = acc[i][3] + bvv[3];
        *(float4*)(y + (size_t)(m0 + tm * 8 + i) * EE + n0 + tn * 4) = o4;
    }
}

// =============================================================================
// Kernel 2: attention with 3xtf32 mma.sync for scores and ctx.
// Per block: (b, h, 32 q rows). 256 threads = 8 warps.
// smem: Qs[32][68] | KV buf (Ks[256][68] / Vs[256][72] / red buf[8][32][68]) |
//       Sc[32][1032]
// =============================================================================
#define QS_PITCH 68
#define KS_PITCH 68
#define VS_PITCH 72
#define SC_PITCH 1032
#define RB_PITCH 68

#define QS_OFF 0
#define KV_OFF (32 * QS_PITCH)                 // 2176
#define KV_FLOATS (256 * VS_PITCH)             // 18432 (max of K/V/redbuf needs)
#define SC_OFF (KV_OFF + KV_FLOATS)            // 20608
#define ATTN_SMEM_FLOATS (SC_OFF + 32 * SC_PITCH)   // 53632
#define ATTN_SMEM_BYTES  (ATTN_SMEM_FLOATS * 4)     // 214528

__global__ __launch_bounds__(256) void attn_kernel(float* __restrict__ probs)
{
    extern __shared__ float sm[];
    float* Qs = sm + QS_OFF;
    float* KV = sm + KV_OFF;
    float* Sc = sm + SC_OFF;

    __shared__ float red[32][8];
    __shared__ float invs[32];

    const int tid  = threadIdx.x;
    const int lane = tid & 31;
    const int w    = tid >> 5;      // warp 0..7
    const int gid  = lane >> 2;     // 0..7
    const int ctid = lane & 3;      // 0..3

    const int qt = blockIdx.x;      // 0..31
    const int bh = blockIdx.y;      // 0..95
    const int b  = bh / NH;
    const int h  = bh % NH;

    const float* qptr  = g_q + ((size_t)b * SS + qt * 32) * EE + h * DD;
    const float* kbase = g_k + (size_t)b * SS * EE + h * DD;
    const float* vbase = g_v + (size_t)b * SS * EE + h * DD;

    // ---- stage Q tile [32][64] -> Qs ----
    #pragma unroll
    for (int p = 0; p < 2; p++) {
        int idx = tid + p * 256;
        int r   = idx >> 4;
        int d4  = (idx & 15) << 2;
        *(float4*)(Qs + r * QS_PITCH + d4) =
            *(const float4*)(qptr + (size_t)r * EE + d4);
    }

    // =================== scores: S = (Q K^T) / 8 ===================
    for (int c = 0; c < 4; c++) {
        __syncthreads();
        const float* kptr = kbase + (size_t)(c * 256) * EE;
        #pragma unroll
        for (int p = 0; p < 16; p++) {
            int idx = tid + p * 256;
            int r   = idx >> 4;
            int d4  = (idx & 15) << 2;
            *(float4*)(KV + r * KS_PITCH + d4) =
                *(const float4*)(kptr + (size_t)r * EE + d4);
        }
        __syncthreads();

        float acc[2][4][4];
        #pragma unroll
        for (int mt = 0; mt < 2; mt++)
            #pragma unroll
            for (int nt = 0; nt < 4; nt++)
                #pragma unroll
                for (int j = 0; j < 4; j++) acc[mt][nt][j] = 0.f;

        #pragma unroll
        for (int k0 = 0; k0 < 64; k0 += 8) {
            uint32_t ah[2][4], al[2][4];
            #pragma unroll
            for (int mt = 0; mt < 2; mt++) {
                const float* qb = Qs + (mt * 16 + gid) * QS_PITCH + k0;
                split_tf32(qb[ctid],                  ah[mt][0], al[mt][0]);
                split_tf32(qb[8 * QS_PITCH + ctid],   ah[mt][1], al[mt][1]);
                split_tf32(qb[ctid + 4],              ah[mt][2], al[mt][2]);
                split_tf32(qb[8 * QS_PITCH + ctid+4], ah[mt][3], al[mt][3]);
            }
            #pragma unroll
            for (int nt = 0; nt < 4; nt++) {
                const float* kb = KV + (w * 32 + nt * 8 + gid) * KS_PITCH + k0;
                uint32_t bhv[2], blv[2];
                split_tf32(kb[ctid],     bhv[0], blv[0]);
                split_tf32(kb[ctid + 4], bhv[1], blv[1]);
                #pragma unroll
                for (int mt = 0; mt < 2; mt++) {
                    mma_tf32(acc[mt][nt], ah[mt], bhv);
                    mma_tf32(acc[mt][nt], ah[mt], blv);
                    mma_tf32(acc[mt][nt], al[mt], bhv);
                }
            }
        }

        // store scaled scores into Sc
        #pragma unroll
        for (int mt = 0; mt < 2; mt++)
            #pragma unroll
            for (int nt = 0; nt < 4; nt++) {
                int colb = c * 256 + w * 32 + nt * 8 + 2 * ctid;
                int r0   = mt * 16 + gid;
                float2 s0 = make_float2(acc[mt][nt][0] * 0.125f, acc[mt][nt][1] * 0.125f);
                float2 s1 = make_float2(acc[mt][nt][2] * 0.125f, acc[mt][nt][3] * 0.125f);
                *(float2*)(Sc + r0 * SC_PITCH + colb)       = s0;
                *(float2*)(Sc + (r0 + 8) * SC_PITCH + colb) = s1;
            }
    }
    __syncthreads();

    // =================== softmax over 32 rows ===================
    {
        const int row = tid >> 3;
        const int j   = tid & 7;
        float mx = -3.4e38f;
        for (int cc = j; cc < 1024; cc += 8) mx = fmaxf(mx, Sc[row * SC_PITCH + cc]);
        red[row][j] = mx;
        __syncthreads();
        #pragma unroll
        for (int t = 0; t < 8; t++) mx = fmaxf(mx, red[row][t]);
        __syncthreads();

        float sum = 0.f;
        for (int cc = j; cc < 1024; cc += 8) {
            float e = __expf(Sc[row * SC_PITCH + cc] - mx);
            Sc[row * SC_PITCH + cc] = e;     // unnormalized
            sum += e;
        }
        red[row][j] = sum;
        __syncthreads();
        float s = 0.f;
        #pragma unroll
        for (int t = 0; t < 8; t++) s += red[row][t];
        if (j == 0) invs[row] = 1.f / s;
    }
    __syncthreads();

    // =================== normalized probs write (coalesced) ===================
    {
        float* pbase = probs + ((size_t)bh * SS + qt * 32) * SS;
        for (int idx = tid; idx < 32 * 1024; idx += 256) {
            int row = idx >> 10;
            int col = idx & 1023;
            pbase[idx] = Sc[row * SC_PITCH + col] * invs[row];
        }
    }

    // =================== ctx = P @ V (k-split across warps) ===================
    float acc2[16][4];   // [mt*8+nt][4]
    #pragma unroll
    for (int i = 0; i < 16; i++)
        #pragma unroll
        for (int j = 0; j < 4; j++) acc2[i][j] = 0.f;

    for (int c = 0; c < 4; c++) {
        __syncthreads();   // prior KV consumers done
        const float* vptr = vbase + (size_t)(c * 256) * EE;
        #pragma unroll
        for (int p = 0; p < 16; p++) {
            int idx = tid + p * 256;
            int r   = idx >> 4;
            int d4  = (idx & 15) << 2;
            *(float4*)(KV + r * VS_PITCH + d4) =
                *(const float4*)(vptr + (size_t)r * EE + d4);
        }
        __syncthreads();

        #pragma unroll
        for (int ks = 0; ks < 4; ks++) {
            int kk = w * 32 + ks * 8;        // key offset within chunk
            uint32_t ah[2][4], al[2][4];
            #pragma unroll
            for (int mt = 0; mt < 2; mt++) {
                const float* sb = Sc + (mt * 16 + gid) * SC_PITCH + c * 256 + kk;
                split_tf32(sb[ctid],                    ah[mt][0], al[mt][0]);
                split_tf32(sb[8 * SC_PITCH + ctid],     ah[mt][1], al[mt][1]);
                split_tf32(sb[ctid + 4],                ah[mt][2], al[mt][2]);
                split_tf32(sb[8 * SC_PITCH + ctid + 4], ah[mt][3], al[mt][3]);
            }
            #pragma unroll
            for (int nt = 0; nt < 8; nt++) {
                const float* vb = KV + (kk + ctid) * VS_PITCH + nt * 8 + gid;
                uint32_t bhv[2], blv[2];
                split_tf32(vb[0],             bhv[0], blv[0]);
                split_tf32(vb[4 * VS_PITCH],  bhv[1], blv[1]);
                #pragma unroll
                for (int mt = 0; mt < 2; mt++) {
                    mma_tf32(acc2[mt * 8 + nt], ah[mt], bhv);
                    mma_tf32(acc2[mt * 8 + nt], ah[mt], blv);
                    mma_tf32(acc2[mt * 8 + nt], al[mt], bhv);
                }
            }
        }
    }
    __syncthreads();

    // ---- cross-warp reduction of 8 partial C[32][64] tiles via KV buffer ----
    float* buf = KV;   // 8 * 32 * RB_PITCH = 17408 floats <= KV_FLOATS
    #pragma unroll
    for (int mt = 0; mt < 2; mt++)
        #pragma unroll
        for (int nt = 0; nt < 8; nt++) {
            int r0   = mt * 16 + gid;
            int colb = nt * 8 + 2 * ctid;
            float* bp = buf + w * (32 * RB_PITCH);
            *(float2*)(bp + r0 * RB_PITCH + colb) =
                make_float2(acc2[mt * 8 + nt][0], acc2[mt * 8 + nt][1]);
            *(float2*)(bp + (r0 + 8) * RB_PITCH + colb) =
                make_float2(acc2[mt * 8 + nt][2], acc2[mt * 8 + nt][3]);
        }
    __syncthreads();

    {
        int e0  = tid * 8;        // element in [32 x 64]
        int row = e0 >> 6;
        int col = e0 & 63;
        float r8[8];
        #pragma unroll
        for (int j = 0; j < 8; j++) r8[j] = 0.f;
        #pragma unroll
        for (int ww = 0; ww < 8; ww++) {
            const float* bp = buf + ww * (32 * RB_PITCH) + row * RB_PITCH + col;
            float4 x0 = *(const float4*)bp;
            float4 x1 = *(const float4*)(bp + 4);
            r8[0] += x0.x; r8[1] += x0.y; r8[2] += x0.z; r8[3] += x0.w;
            r8[4] += x1.x; r8[5] += x1.y; r8[6] += x1.z; r8[7] += x1.w;
        }
        float ci = invs[row];
        float* op = g_ctx + ((size_t)b * SS + qt * 32 + row) * EE + h * DD + col;
        float4 o0 = make_float4(r8[0] * ci, r8[1] * ci, r8[2] * ci, r8[3] * ci);
        float4 o1 = make_float4(r8[4] * ci, r8[5] * ci, r8[6] * ci, r8[7] * ci);
        *(float4*)op       = o0;
        *(float4*)(op + 4) = o1;
    }
}

// =============================================================================
// Kernel 3: output projection (unchanged from round 1)
// =============================================================================
__global__ __launch_bounds__(256) void fc_kernel(
    const float* __restrict__ fcw, const float* __restrict__ fcb,
    float* __restrict__ out)
{
    const int b  = blockIdx.z;
    const int m0 = blockIdx.x * BM;
    const int n0 = blockIdx.y * BN;

    const float* ctx = g_ctx + (size_t)b * SS * EE;

    __shared__ float As[BK][BM];
    __shared__ float Bs[BK][BN];

    const int tid = threadIdx.x;
    const int tn = tid & 15;
    const int tm = tid >> 4;

    float acc[8][4];
    #pragma unroll
    for (int i = 0; i < 8; i++)
        #pragma unroll
        for (int j = 0; j < 4; j++) acc[i][j] = 0.f;

    for (int k0 = 0; k0 < EE; k0 += BK) {
        #pragma unroll
        for (int p = 0; p < 2; p++) {
            int idx = tid + p * 256;
            int row = idx >> 2;
            int kq  = (idx & 3) << 2;
            float4 v4 = *(const float4*)(fcw + (size_t)(m0 + row) * EE + k0 + kq);
            As[kq + 0][row] = v4.x; As[kq + 1][row] = v4.y;
            As[kq + 2][row] = v4.z; As[kq + 3][row] = v4.w;
        }
        {
            int r  = tid >> 2;
            int kq = (tid & 3) << 2;
            float4 v4 = *(const float4*)(ctx + (size_t)(n0 + r) * EE + k0 + kq);
            Bs[kq + 0][r] = v4.x; Bs[kq + 1][r] = v4.y;
            Bs[kq + 2][r] = v4.z; Bs[kq + 3][r] = v4.w;
        }
        __syncthreads();

        #pragma unroll
        for (int kk = 0; kk < BK; kk++) {
            float a[8], bb[4];
            *(float4*)&a[0] = *(float4*)&As[kk][tm * 8];
            *(float4*)&a[4] = *(float4*)&As[kk][tm * 8 + 4];
            *(float4*)&bb[0] = *(float4*)&Bs[kk][tn * 4];
            #pragma unroll
            for (int i = 0; i < 8; i++)
                #pragma unroll
                for (int j = 0; j < 4; j++)
                    acc[i][j] += a[i] * bb[j];
        }
        __syncthreads();
    }

    #pragma unroll
    for (int i = 0; i < 8; i++) {
        int o = m0 + tm * 8 + i;
        float fb = fcb[o];
        float4 o4;
        o4.x = acc[i][0] + fb; o4.y = acc[i][1] + fb;
        o4.z = acc[i][2] + fb; o4.w = acc[i][3] + fb;
        *(float4*)(out + ((size_t)b * EE + o) * SS + n0 + tn * 4) = o4;
    }
}

// =============================================================================
extern "C" void kernel_launch(void* const* d_in, const int* in_sizes, int n_in,
                              void* d_out, int out_size)
{
    const float* q_img = (const float*)d_in[0];
    const float* k_img = (const float*)d_in[1];
    const float* v_img = (const float*)d_in[2];
    const float* wq_w  = (const float*)d_in[3];
    const float* wq_b  = (const float*)d_in[4];
    const float* wk_w  = (const float*)d_in[5];
    const float* wk_b  = (const float*)d_in[6];
    const float* wv_w  = (const float*)d_in[7];
    const float* wv_b  = (const float*)d_in[8];
    const float* fc_w  = (const float*)d_in[9];
    const float* fc_b  = (const float*)d_in[10];

    float* out   = (float*)d_out;
    float* probs = out + (size_t)BB * EE * SS;   // tuple output: (out, probs)

    // 1) QKV projections
    dim3 g1(SS / BM, EE / BN, 3 * BB);
    proj_kernel<<<g1, 256>>>(q_img, k_img, v_img,
                             wq_w, wk_w, wv_w,
                             wq_b, wk_b, wv_b);

    // 2) attention (+ probs output)
    cudaFuncSetAttribute(attn_kernel, cudaFuncAttributeMaxDynamicSharedMemorySize,
                         ATTN_SMEM_BYTES);
    attn_kernel<<<dim3(SS / 32, BB * NH), 256, ATTN_SMEM_BYTES>>>(probs);

    // 3) output projection
    fc_kernel<<<dim3(EE / BM, SS / BN, BB), 256>>>(fc_w, fc_b, out);
}

// round 3
// speedup vs baseline: 1.8144x; 1.1769x over previous
#include <cuda_runtime.h>
#include <cuda_bf16.h>
#include <cstdint>

// Problem dims
#define BB 8
#define SS 1024          // IMG*IMG
#define EE 768           // D_EMBED == D_MODEL
#define NH 12
#define DD 64

// ---------------- scratch (device globals; no allocs allowed) ----------------
__device__ float g_q[BB * SS * EE];
__device__ float g_k[BB * SS * EE];
__device__ float g_v[BB * SS * EE];
__device__ float g_ctx[BB * SS * EE];

// =============================================================================
// tf32 helpers
// =============================================================================
__device__ __forceinline__ void split_tf32(float x, uint32_t& hi, uint32_t& lo) {
    asm("cvt.rna.tf32.f32 %0, %1;" : "=r"(hi) : "f"(x));
    float r = x - __uint_as_float(hi);
    asm("cvt.rna.tf32.f32 %0, %1;" : "=r"(lo) : "f"(r));
}
__device__ __forceinline__ void split_tf32_f(float x, float& hi, float& lo) {
    uint32_t h, l; split_tf32(x, h, l);
    hi = __uint_as_float(h); lo = __uint_as_float(l);
}

__device__ __forceinline__ void mma_tf32(float* d, const uint32_t* a, const uint32_t* b) {
    asm volatile(
        "mma.sync.aligned.m16n8k8.row.col.f32.tf32.tf32.f32 "
        "{%0,%1,%2,%3}, {%4,%5,%6,%7}, {%8,%9}, {%0,%1,%2,%3};"
        : "+f"(d[0]), "+f"(d[1]), "+f"(d[2]), "+f"(d[3])
        : "r"(a[0]), "r"(a[1]), "r"(a[2]), "r"(a[3]),
          "r"(b[0]), "r"(b[1]));
}
#define F2U(p) (*(const uint32_t*)&(p))

// =============================================================================
// Kernel 1: QKV projection via 3xtf32 mma, staged hi/lo in smem.
//   Y[s,o] = sum_c X[b][c][s] * W[o][c] + bias[o]
// A = X^T : gmem [k][m] (m contiguous) -> smem As[k][m] pitch 136 (direct)
// B = W   : gmem [n][k] (k contiguous) -> smem Bs[n][k] pitch 36  (direct)
// Block tile: 128m x 64n x 32k. 8 warps = 4(m) x 2(n), each 32x32.
// =============================================================================
#define GP_AP 136
#define GP_BP 36
#define GP_AH 0
#define GP_AL 4352          // 32*136
#define GP_BH 8704
#define GP_BL 11008         // +64*36
#define GP_SMEM_FLOATS 13312
#define GP_SMEM_BYTES (GP_SMEM_FLOATS * 4)

__global__ __launch_bounds__(256) void proj_mma_kernel(
    const float* __restrict__ xq, const float* __restrict__ xk, const float* __restrict__ xv,
    const float* __restrict__ wq, const float* __restrict__ wk, const float* __restrict__ wv,
    const float* __restrict__ bq, const float* __restrict__ bk, const float* __restrict__ bv)
{
    extern __shared__ float sp[];
    float* AH = sp + GP_AH;
    float* AL = sp + GP_AL;
    float* BH = sp + GP_BH;
    float* BL = sp + GP_BL;

    const int mat = blockIdx.z >> 3;
    const int b   = blockIdx.z & 7;

    const float* x; const float* w; const float* bi; float* y;
    if (mat == 0)      { x = xq; w = wq; bi = bq; y = g_q; }
    else if (mat == 1) { x = xk; w = wk; bi = bk; y = g_k; }
    else               { x = xv; w = wv; bi = bv; y = g_v; }
    x += (size_t)b * EE * SS;
    y += (size_t)b * SS * EE;

    const int m0 = blockIdx.x * 128;
    const int n0 = blockIdx.y * 64;

    const int tid  = threadIdx.x;
    const int lane = tid & 31;
    const int w8   = tid >> 5;
    const int wm   = w8 >> 1;        // 0..3
    const int wn   = w8 & 1;         // 0..1
    const int gid  = lane >> 2;
    const int ctid = lane & 3;

    float acc[2][4][4];
    #pragma unroll
    for (int i = 0; i < 2; i++)
        #pragma unroll
        for (int j = 0; j < 4; j++)
            #pragma unroll
            for (int q = 0; q < 4; q++) acc[i][j][q] = 0.f;

    for (int kg = 0; kg < EE; kg += 32) {
        __syncthreads();
        // stage A: X rows [kg..kg+32), cols [m0..m0+128) -> As[k][m]
        #pragma unroll
        for (int p = 0; p < 4; p++) {
            int idx = tid + p * 256;
            int kr  = idx >> 5;
            int mc  = (idx & 31) << 2;
            float4 v4 = *(const float4*)(x + (size_t)(kg + kr) * SS + m0 + mc);
            float h, l;
            split_tf32_f(v4.x, h, l); AH[kr*GP_AP + mc + 0] = h; AL[kr*GP_AP + mc + 0] = l;
            split_tf32_f(v4.y, h, l); AH[kr*GP_AP + mc + 1] = h; AL[kr*GP_AP + mc + 1] = l;
            split_tf32_f(v4.z, h, l); AH[kr*GP_AP + mc + 2] = h; AL[kr*GP_AP + mc + 2] = l;
            split_tf32_f(v4.w, h, l); AH[kr*GP_AP + mc + 3] = h; AL[kr*GP_AP + mc + 3] = l;
        }
        // stage B: W rows [n0..n0+64), k cols [kg..kg+32) -> Bs[n][k]
        #pragma unroll
        for (int p = 0; p < 2; p++) {
            int idx = tid + p * 256;
            int r   = idx >> 3;
            int kc  = (idx & 7) << 2;
            float4 v4 = *(const float4*)(w + (size_t)(n0 + r) * EE + kg + kc);
            float h, l;
            split_tf32_f(v4.x, h, l); BH[r*GP_BP + kc + 0] = h; BL[r*GP_BP + kc + 0] = l;
            split_tf32_f(v4.y, h, l); BH[r*GP_BP + kc + 1] = h; BL[r*GP_BP + kc + 1] = l;
            split_tf32_f(v4.z, h, l); BH[r*GP_BP + kc + 2] = h; BL[r*GP_BP + kc + 2] = l;
            split_tf32_f(v4.w, h, l); BH[r*GP_BP + kc + 3] = h; BL[r*GP_BP + kc + 3] = l;
        }
        __syncthreads();

        #pragma unroll
        for (int k0 = 0; k0 < 32; k0 += 8) {
            uint32_t ah[2][4], al[2][4];
            #pragma unroll
            for (int mt = 0; mt < 2; mt++) {
                int mrow = wm * 32 + mt * 16 + gid;
                const float* ph = AH + (k0 + ctid) * GP_AP + mrow;
                const float* pl = AL + (k0 + ctid) * GP_AP + mrow;
                ah[mt][0] = F2U(ph[0]);          ah[mt][1] = F2U(ph[8]);
                ah[mt][2] = F2U(ph[4*GP_AP]);    ah[mt][3] = F2U(ph[4*GP_AP + 8]);
                al[mt][0] = F2U(pl[0]);          al[mt][1] = F2U(pl[8]);
                al[mt][2] = F2U(pl[4*GP_AP]);    al[mt][3] = F2U(pl[4*GP_AP + 8]);
            }
            #pragma unroll
            for (int nt = 0; nt < 4; nt++) {
                int nrow = wn * 32 + nt * 8 + gid;
                uint32_t bh[2], bl[2];
                bh[0] = F2U(BH[nrow*GP_BP + k0 + ctid]);
                bh[1] = F2U(BH[nrow*GP_BP + k0 + ctid + 4]);
                bl[0] = F2U(BL[nrow*GP_BP + k0 + ctid]);
                bl[1] = F2U(BL[nrow*GP_BP + k0 + ctid + 4]);
                #pragma unroll
                for (int mt = 0; mt < 2; mt++) {
                    mma_tf32(acc[mt][nt], ah[mt], bh);
                    mma_tf32(acc[mt][nt], ah[mt], bl);
                    mma_tf32(acc[mt][nt], al[mt], bh);
                }
            }
        }
    }

    // epilogue
    #pragma unroll
    for (int nt = 0; nt < 4; nt++) {
        int col = n0 + wn * 32 + nt * 8 + 2 * ctid;
        float b0 = bi[col], b1 = bi[col + 1];
        #pragma unroll
        for (int mt = 0; mt < 2; mt++) {
            int row = m0 + wm * 32 + mt * 16 + gid;
            *(float2*)(y + (size_t)row * EE + col) =
                make_float2(acc[mt][nt][0] + b0, acc[mt][nt][1] + b1);
            *(float2*)(y + (size_t)(row + 8) * EE + col) =
                make_float2(acc[mt][nt][2] + b0, acc[mt][nt][3] + b1);
        }
    }
}

// =============================================================================
// Kernel 2: attention (unchanged from round 2)
// =============================================================================
#define QS_PITCH 68
#define KS_PITCH 68
#define VS_PITCH 72
#define SC_PITCH 1032
#define RB_PITCH 68

#define QS_OFF 0
#define KV_OFF (32 * QS_PITCH)
#define KV_FLOATS (256 * VS_PITCH)
#define SC_OFF (KV_OFF + KV_FLOATS)
#define ATTN_SMEM_FLOATS (SC_OFF + 32 * SC_PITCH)
#define ATTN_SMEM_BYTES  (ATTN_SMEM_FLOATS * 4)

__global__ __launch_bounds__(256) void attn_kernel(float* __restrict__ probs)
{
    extern __shared__ float sm[];
    float* Qs = sm + QS_OFF;
    float* KV = sm + KV_OFF;
    float* Sc = sm + SC_OFF;

    __shared__ float red[32][8];
    __shared__ float invs[32];

    const int tid  = threadIdx.x;
    const int lane = tid & 31;
    const int w    = tid >> 5;
    const int gid  = lane >> 2;
    const int ctid = lane & 3;

    const int qt = blockIdx.x;
    const int bh = blockIdx.y;
    const int b  = bh / NH;
    const int h  = bh % NH;

    const float* qptr  = g_q + ((size_t)b * SS + qt * 32) * EE + h * DD;
    const float* kbase = g_k + (size_t)b * SS * EE + h * DD;
    const float* vbase = g_v + (size_t)b * SS * EE + h * DD;

    #pragma unroll
    for (int p = 0; p < 2; p++) {
        int idx = tid + p * 256;
        int r   = idx >> 4;
        int d4  = (idx & 15) << 2;
        *(float4*)(Qs + r * QS_PITCH + d4) =
            *(const float4*)(qptr + (size_t)r * EE + d4);
    }

    // scores
    for (int c = 0; c < 4; c++) {
        __syncthreads();
        const float* kptr = kbase + (size_t)(c * 256) * EE;
        #pragma unroll
        for (int p = 0; p < 16; p++) {
            int idx = tid + p * 256;
            int r   = idx >> 4;
            int d4  = (idx & 15) << 2;
            *(float4*)(KV + r * KS_PITCH + d4) =
                *(const float4*)(kptr + (size_t)r * EE + d4);
        }
        __syncthreads();

        float acc[2][4][4];
        #pragma unroll
        for (int i = 0; i < 2; i++)
            #pragma unroll
            for (int j = 0; j < 4; j++)
                #pragma unroll
                for (int q = 0; q < 4; q++) acc[i][j][q] = 0.f;

        #pragma unroll
        for (int k0 = 0; k0 < 64; k0 += 8) {
            uint32_t ah[2][4], al[2][4];
            #pragma unroll
            for (int mt = 0; mt < 2; mt++) {
                const float* qb = Qs + (mt * 16 + gid) * QS_PITCH + k0;
                split_tf32(qb[ctid],                  ah[mt][0], al[mt][0]);
                split_tf32(qb[8 * QS_PITCH + ctid],   ah[mt][1], al[mt][1]);
                split_tf32(qb[ctid + 4],              ah[mt][2], al[mt][2]);
                split_tf32(qb[8 * QS_PITCH + ctid+4], ah[mt][3], al[mt][3]);
            }
            #pragma unroll
            for (int nt = 0; nt < 4; nt++) {
                const float* kb = KV + (w * 32 + nt * 8 + gid) * KS_PITCH + k0;
                uint32_t bhv[2], blv[2];
                split_tf32(kb[ctid],     bhv[0], blv[0]);
                split_tf32(kb[ctid + 4], bhv[1], blv[1]);
                #pragma unroll
                for (int mt = 0; mt < 2; mt++) {
                    mma_tf32(acc[mt][nt], ah[mt], bhv);
                    mma_tf32(acc[mt][nt], ah[mt], blv);
                    mma_tf32(acc[mt][nt], al[mt], bhv);
                }
            }
        }

        #pragma unroll
        for (int mt = 0; mt < 2; mt++)
            #pragma unroll
            for (int nt = 0; nt < 4; nt++) {
                int colb = c * 256 + w * 32 + nt * 8 + 2 * ctid;
                int r0   = mt * 16 + gid;
                *(float2*)(Sc + r0 * SC_PITCH + colb) =
                    make_float2(acc[mt][nt][0] * 0.125f, acc[mt][nt][1] * 0.125f);
                *(float2*)(Sc + (r0 + 8) * SC_PITCH + colb) =
                    make_float2(acc[mt][nt][2] * 0.125f, acc[mt][nt][3] * 0.125f);
            }
    }
    __syncthreads();

    // softmax
    {
        const int row = tid >> 3;
        const int j   = tid & 7;
        float mx = -3.4e38f;
        for (int cc = j; cc < 1024; cc += 8) mx = fmaxf(mx, Sc[row * SC_PITCH + cc]);
        red[row][j] = mx;
        __syncthreads();
        #pragma unroll
        for (int t = 0; t < 8; t++) mx = fmaxf(mx, red[row][t]);
        __syncthreads();

        float sum = 0.f;
        for (int cc = j; cc < 1024; cc += 8) {
            float e = __expf(Sc[row * SC_PITCH + cc] - mx);
            Sc[row * SC_PITCH + cc] = e;
            sum += e;
        }
        red[row][j] = sum;
        __syncthreads();
        float s = 0.f;
        #pragma unroll
        for (int t = 0; t < 8; t++) s += red[row][t];
        if (j == 0) invs[row] = 1.f / s;
    }
    __syncthreads();

    // probs write
    {
        float* pbase = probs + ((size_t)bh * SS + qt * 32) * SS;
        for (int idx = tid; idx < 32 * 1024; idx += 256) {
            int row = idx >> 10;
            int col = idx & 1023;
            pbase[idx] = Sc[row * SC_PITCH + col] * invs[row];
        }
    }

    // ctx = P @ V
    float acc2[16][4];
    #pragma unroll
    for (int i = 0; i < 16; i++)
        #pragma unroll
        for (int j = 0; j < 4; j++) acc2[i][j] = 0.f;

    for (int c = 0; c < 4; c++) {
        __syncthreads();
        const float* vptr = vbase + (size_t)(c * 256) * EE;
        #pragma unroll
        for (int p = 0; p < 16; p++) {
            int idx = tid + p * 256;
            int r   = idx >> 4;
            int d4  = (idx & 15) << 2;
            *(float4*)(KV + r * VS_PITCH + d4) =
                *(const float4*)(vptr + (size_t)r * EE + d4);
        }
        __syncthreads();

        #pragma unroll
        for (int ks = 0; ks < 4; ks++) {
            int kk = w * 32 + ks * 8;
            uint32_t ah[2][4], al[2][4];
            #pragma unroll
            for (int mt = 0; mt < 2; mt++) {
                const float* sb = Sc + (mt * 16 + gid) * SC_PITCH + c * 256 + kk;
                split_tf32(sb[ctid],                    ah[mt][0], al[mt][0]);
                split_tf32(sb[8 * SC_PITCH + ctid],     ah[mt][1], al[mt][1]);
                split_tf32(sb[ctid + 4],                ah[mt][2], al[mt][2]);
                split_tf32(sb[8 * SC_PITCH + ctid + 4], ah[mt][3], al[mt][3]);
            }
            #pragma unroll
            for (int nt = 0; nt < 8; nt++) {
                const float* vb = KV + (kk + ctid) * VS_PITCH + nt * 8 + gid;
                uint32_t bhv[2], blv[2];
                split_tf32(vb[0],            bhv[0], blv[0]);
                split_tf32(vb[4 * VS_PITCH], bhv[1], blv[1]);
                #pragma unroll
                for (int mt = 0; mt < 2; mt++) {
                    mma_tf32(acc2[mt * 8 + nt], ah[mt], bhv);
                    mma_tf32(acc2[mt * 8 + nt], ah[mt], blv);
                    mma_tf32(acc2[mt * 8 + nt], al[mt], bhv);
                }
            }
        }
    }
    __syncthreads();

    float* buf = KV;
    #pragma unroll
    for (int mt = 0; mt < 2; mt++)
        #pragma unroll
        for (int nt = 0; nt < 8; nt++) {
            int r0   = mt * 16 + gid;
            int colb = nt * 8 + 2 * ctid;
            float* bp = buf + w * (32 * RB_PITCH);
            *(float2*)(bp + r0 * RB_PITCH + colb) =
                make_float2(acc2[mt * 8 + nt][0], acc2[mt * 8 + nt][1]);
            *(float2*)(bp + (r0 + 8) * RB_PITCH + colb) =
                make_float2(acc2[mt * 8 + nt][2], acc2[mt * 8 + nt][3]);
        }
    __syncthreads();

    {
        int e0  = tid * 8;
        int row = e0 >> 6;
        int col = e0 & 63;
        float r8[8];
        #pragma unroll
        for (int j = 0; j < 8; j++) r8[j] = 0.f;
        #pragma unroll
        for (int ww = 0; ww < 8; ww++) {
            const float* bp = buf + ww * (32 * RB_PITCH) + row * RB_PITCH + col;
            float4 x0 = *(const float4*)bp;
            float4 x1 = *(const float4*)(bp + 4);
            r8[0] += x0.x; r8[1] += x0.y; r8[2] += x0.z; r8[3] += x0.w;
            r8[4] += x1.x; r8[5] += x1.y; r8[6] += x1.z; r8[7] += x1.w;
        }
        float ci = invs[row];
        float* op = g_ctx + ((size_t)b * SS + qt * 32 + row) * EE + h * DD + col;
        *(float4*)op       = make_float4(r8[0]*ci, r8[1]*ci, r8[2]*ci, r8[3]*ci);
        *(float4*)(op + 4) = make_float4(r8[4]*ci, r8[5]*ci, r8[6]*ci, r8[7]*ci);
    }
}

// =============================================================================
// Kernel 3: output projection via 3xtf32 mma.
//   out[b][o][s] = sum_c ctx[b][s][c] * fc_w[o][c] + fc_b[o]
// M=o(768), N=s(1024). A = fc_w [m][k] -> smem As[m][k] pitch 36 (direct).
// B = ctx [n][k]  -> smem Bs[n][k] pitch 36 (direct).
// Block tile: 128m x 64n x 32k.
// =============================================================================
#define GF_AP 36
#define GF_AH 0
#define GF_AL 4608          // 128*36
#define GF_BH 9216
#define GF_BL 11520         // +64*36
#define GF_SMEM_FLOATS 13824
#define GF_SMEM_BYTES (GF_SMEM_FLOATS * 4)

__global__ __launch_bounds__(256) void fc_mma_kernel(
    const float* __restrict__ fcw, const float* __restrict__ fcb,
    float* __restrict__ out)
{
    extern __shared__ float sp[];
    float* AH = sp + GF_AH;
    float* AL = sp + GF_AL;
    float* BH = sp + GF_BH;
    float* BL = sp + GF_BL;

    const int b  = blockIdx.z;
    const int m0 = blockIdx.x * 128;   // o
    const int n0 = blockIdx.y * 64;    // s

    const float* ctx = g_ctx + (size_t)b * SS * EE;

    const int tid  = threadIdx.x;
    const int lane = tid & 31;
    const int w8   = tid >> 5;
    const int wm   = w8 >> 1;
    const int wn   = w8 & 1;
    const int gid  = lane >> 2;
    const int ctid = lane & 3;

    float acc[2][4][4];
    #pragma unroll
    for (int i = 0; i < 2; i++)
        #pragma unroll
        for (int j = 0; j < 4; j++)
            #pragma unroll
            for (int q = 0; q < 4; q++) acc[i][j][q] = 0.f;

    for (int kg = 0; kg < EE; kg += 32) {
        __syncthreads();
        // stage A (fc_w): 128 rows x 32 k -> As[m][k]
        #pragma unroll
        for (int p = 0; p < 4; p++) {
            int idx = tid + p * 256;
            int r   = idx >> 3;
            int kc  = (idx & 7) << 2;
            float4 v4 = *(const float4*)(fcw + (size_t)(m0 + r) * EE + kg + kc);
            float h, l;
            split_tf32_f(v4.x, h, l); AH[r*GF_AP + kc + 0] = h; AL[r*GF_AP + kc + 0] = l;
            split_tf32_f(v4.y, h, l); AH[r*GF_AP + kc + 1] = h; AL[r*GF_AP + kc + 1] = l;
            split_tf32_f(v4.z, h, l); AH[r*GF_AP + kc + 2] = h; AL[r*GF_AP + kc + 2] = l;
            split_tf32_f(v4.w, h, l); AH[r*GF_AP + kc + 3] = h; AL[r*GF_AP + kc + 3] = l;
        }
        // stage B (ctx): 64 rows x 32 k -> Bs[n][k]
        #pragma unroll
        for (int p = 0; p < 2; p++) {
            int idx = tid + p * 256;
            int r   = idx >> 3;
            int kc  = (idx & 7) << 2;
            float4 v4 = *(const float4*)(ctx + (size_t)(n0 + r) * EE + kg + kc);
            float h, l;
            split_tf32_f(v4.x, h, l); BH[r*GF_AP + kc + 0] = h; BL[r*GF_AP + kc + 0] = l;
            split_tf32_f(v4.y, h, l); BH[r*GF_AP + kc + 1] = h; BL[r*GF_AP + kc + 1] = l;
            split_tf32_f(v4.z, h, l); BH[r*GF_AP + kc + 2] = h; BL[r*GF_AP + kc + 2] = l;
            split_tf32_f(v4.w, h, l); BH[r*GF_AP + kc + 3] = h; BL[r*GF_AP + kc + 3] = l;
        }
        __syncthreads();

        #pragma unroll
        for (int k0 = 0; k0 < 32; k0 += 8) {
            uint32_t ah[2][4], al[2][4];
            #pragma unroll
            for (int mt = 0; mt < 2; mt++) {
                int mrow = wm * 32 + mt * 16 + gid;
                const float* ph = AH + mrow * GF_AP + k0 + ctid;
                const float* pl = AL + mrow * GF_AP + k0 + ctid;
                ah[mt][0] = F2U(ph[0]);              ah[mt][1] = F2U(ph[8*GF_AP]);
                ah[mt][2] = F2U(ph[4]);              ah[mt][3] = F2U(ph[8*GF_AP + 4]);
                al[mt][0] = F2U(pl[0]);              al[mt][1] = F2U(pl[8*GF_AP]);
                al[mt][2] = F2U(pl[4]);              al[mt][3] = F2U(pl[8*GF_AP + 4]);
            }
            #pragma unroll
            for (int nt = 0; nt < 4; nt++) {
                int nrow = wn * 32 + nt * 8 + gid;
                uint32_t bh[2], bl[2];
                bh[0] = F2U(BH[nrow*GF_AP + k0 + ctid]);
                bh[1] = F2U(BH[nrow*GF_AP + k0 + ctid + 4]);
                bl[0] = F2U(BL[nrow*GF_AP + k0 + ctid]);
                bl[1] = F2U(BL[nrow*GF_AP + k0 + ctid + 4]);
                #pragma unroll
                for (int mt = 0; mt < 2; mt++) {
                    mma_tf32(acc[mt][nt], ah[mt], bh);
                    mma_tf32(acc[mt][nt], ah[mt], bl);
                    mma_tf32(acc[mt][nt], al[mt], bh);
                }
            }
        }
    }

    // epilogue: out[(b*EE + o)*SS + s] + fcb[o]
    #pragma unroll
    for (int mt = 0; mt < 2; mt++) {
        int row = m0 + wm * 32 + mt * 16 + gid;
        float fb0 = fcb[row];
        float fb1 = fcb[row + 8];
        #pragma unroll
        for (int nt = 0; nt < 4; nt++) {
            int col = n0 + wn * 32 + nt * 8 + 2 * ctid;
            *(float2*)(out + ((size_t)b * EE + row) * SS + col) =
                make_float2(acc[mt][nt][0] + fb0, acc[mt][nt][1] + fb0);
            *(float2*)(out + ((size_t)b * EE + row + 8) * SS + col) =
                make_float2(acc[mt][nt][2] + fb1, acc[mt][nt][3] + fb1);
        }
    }
}

// =============================================================================
extern "C" void kernel_launch(void* const* d_in, const int* in_sizes, int n_in,
                              void* d_out, int out_size)
{
    const float* q_img = (const float*)d_in[0];
    const float* k_img = (const float*)d_in[1];
    const float* v_img = (const float*)d_in[2];
    const float* wq_w  = (const float*)d_in[3];
    const float* wq_b  = (const float*)d_in[4];
    const float* wk_w  = (const float*)d_in[5];
    const float* wk_b  = (const float*)d_in[6];
    const float* wv_w  = (const float*)d_in[7];
    const float* wv_b  = (const float*)d_in[8];
    const float* fc_w  = (const float*)d_in[9];
    const float* fc_b  = (const float*)d_in[10];

    float* out   = (float*)d_out;
    float* probs = out + (size_t)BB * EE * SS;   // tuple output: (out, probs)

    cudaFuncSetAttribute(proj_mma_kernel, cudaFuncAttributeMaxDynamicSharedMemorySize,
                         GP_SMEM_BYTES);
    cudaFuncSetAttribute(attn_kernel, cudaFuncAttributeMaxDynamicSharedMemorySize,
                         ATTN_SMEM_BYTES);
    cudaFuncSetAttribute(fc_mma_kernel, cudaFuncAttributeMaxDynamicSharedMemorySize,
                         GF_SMEM_BYTES);

    // 1) QKV projections (tf32 mma)
    proj_mma_kernel<<<dim3(SS / 128, EE / 64, 3 * BB), 256, GP_SMEM_BYTES>>>(
        q_img, k_img, v_img, wq_w, wk_w, wv_w, wq_b, wk_b, wv_b);

    // 2) attention (+ probs output)
    attn_kernel<<<dim3(SS / 32, BB * NH), 256, ATTN_SMEM_BYTES>>>(probs);

    // 3) output projection (tf32 mma)
    fc_mma_kernel<<<dim3(EE / 128, SS / 64, BB), 256, GF_SMEM_BYTES>>>(fc_w, fc_b, out);
}